// round 16
// baseline (speedup 1.0000x reference)
#include <cuda_runtime.h>
#include <cuda_fp16.h>
#include <cstdint>

#define D 1024
#define WARPS 2          // warps per block (64 threads), 2 rows per warp
#define BLOCKS_PER_SM 8  // 64 thr x 8 blocks -> 128 regs, 16 warps/SM, 8 staggered CTAs

typedef unsigned long long u64;

// ---------- packed f32x2 helpers (sm_103a) ----------
__device__ __forceinline__ u64 pack2(float a, float b) {
    u64 r; asm("mov.b64 %0, {%1, %2};" : "=l"(r) : "f"(a), "f"(b)); return r;
}
__device__ __forceinline__ void unpack2(u64 v, float& a, float& b) {
    asm("mov.b64 {%0, %1}, %2;" : "=f"(a), "=f"(b) : "l"(v));
}
__device__ __forceinline__ u64 add2(u64 a, u64 b) {
    u64 r; asm("add.rn.f32x2 %0, %1, %2;" : "=l"(r) : "l"(a), "l"(b)); return r;
}
__device__ __forceinline__ u64 mul2(u64 a, u64 b) {
    u64 r; asm("mul.rn.f32x2 %0, %1, %2;" : "=l"(r) : "l"(a), "l"(b)); return r;
}
__device__ __forceinline__ u64 fma2(u64 a, u64 b, u64 c) {
    u64 r; asm("fma.rn.f32x2 %0, %1, %2, %3;" : "=l"(r) : "l"(a), "l"(b), "l"(c)); return r;
}
__device__ __forceinline__ unsigned h2u(__half2 h) { return *reinterpret_cast<unsigned*>(&h); }
__device__ __forceinline__ __half2 u2h(unsigned u) { return *reinterpret_cast<__half2*>(&u); }
// word w = {lo: rowA, hi: rowB}
__device__ __forceinline__ unsigned mkw(float a, float b) { return h2u(__floats2half2_rn(a, b)); }
__device__ __forceinline__ float wlo(unsigned w) { return __low2float(u2h(w)); }
__device__ __forceinline__ float whi(unsigned w) { return __high2float(u2h(w)); }

// FWHT over the 32-value register axis. v[k] packs index i = 2k (lo), 2k+1 (hi).
__device__ __forceinline__ void fwht32(u64 v[16]) {
    const u64 NEG1 = 0xBF800000BF800000ULL;  // (-1.f, -1.f)
    #pragma unroll
    for (int k = 0; k < 16; k++) {
        float a, b; unpack2(v[k], a, b);
        v[k] = pack2(a + b, a - b);
    }
    #pragma unroll
    for (int h = 1; h <= 8; h <<= 1) {
        #pragma unroll
        for (int k = 0; k < 16; k++) {
            if (!(k & h)) {
                u64 A = v[k], B = v[k + h];
                v[k]     = add2(A, B);
                v[k + h] = fma2(B, NEG1, A);
            }
        }
    }
}

// Ownerships: "natural": lane owns z = q*128 + 4*lane + b, regs i = b|(q<<2)
// (= z-bits {0,1,7,8,9}).  "QB": lane = ((z>>7)<<2)|(z&3), regs m = (z>>2)&31.
// All smem in u32 words (one per element, 2 rows packed), word-granularity
// conflict-free layouts.

// Precomputed tables (allocation-free scratch):
__device__ unsigned short g_Qs[D];   // scatter targets (u32-word slot indices)
__device__ __half         g_Gh[D];   // G[t], gather-owner layout (fp16)
__device__ __half         g_Sh[D];   // S[t]/32, natural order (fp16)
__device__ unsigned       g_Bbits[32];  // sign bits of B, natural ownership

__global__ void fastfood_prep(const int* __restrict__ P, const float* __restrict__ B,
                              const float* __restrict__ G, const float* __restrict__ S) {
    int t = blockIdx.x * blockDim.x + threadIdx.x;
    if (t < D) {
        int e  = P[t];
        int w  = ((e >> 7) << 2) | (e & 3);   // writer lane of e (QB)
        int mw = (e >> 2) & 31;               // writer reg of e
        int L  = ((t >> 7) << 2) | (t & 3);   // gather owner lane of t (QB)
        int mm = (t >> 2) & 31;               // gather reg of t
        // gather layout (word units): lane L's 32 words contiguous, uint4-column XOR swizzle
        int slot = L * 32 + ((((mm >> 2) ^ (L & 7)) & 7) << 2) + (mm & 3);
        g_Qs[(mw >> 3) * 256 + w * 8 + (mw & 7)] = (unsigned short)slot;
        g_Gh[((mm >> 2) * 32 + L) * 4 + (mm & 3)] = __float2half(G[t]);
        g_Sh[t] = __float2half(S[t] * 0.03125f);   // 1/sqrt(1024), SCALE=1
    }
    if (t < 32) {
        unsigned bits = 0;
        for (int q = 0; q < 8; q++)
            for (int b = 0; b < 4; b++)
                if (B[q * 128 + 4 * t + b] < 0.0f) bits |= 1u << (4 * q + b);
        g_Bbits[t] = bits;
    }
}

__global__ __launch_bounds__(WARPS * 32, BLOCKS_PER_SM)
void fastfood_kernel(const float* __restrict__ x, float* __restrict__ out, int nrows) {
    __shared__ __align__(16) unsigned buf[WARPS][D];   // 4 KB/warp, 8 KB/block
    const int warp = threadIdx.x >> 5;
    const int lane = threadIdx.x & 31;
    const int pair = blockIdx.x * WARPS + warp;
    if (pair * 2 >= nrows) return;

    unsigned* sw  = buf[warp];
    uint4*    sw4 = reinterpret_cast<uint4*>(sw);
    const int qr = lane >> 2, br = lane & 3;

    const unsigned bb = g_Bbits[lane];

    u64 va[16], vb[16];

    // ---- load both rows, apply B as sign-bit XOR (natural ownership of e) ----
    const float4* xa = reinterpret_cast<const float4*>(x) + (size_t)(pair * 2) * (D / 4) + lane;
    const float4* xb = xa + (D / 4);
    #pragma unroll
    for (int q = 0; q < 8; q++) {
        float4 fa = xa[q * 32];
        float4 fb = xb[q * 32];
        unsigned nib = bb >> (4 * q);
        u64 m0 = (((u64)(nib & 1u)) << 31) | (((u64)(nib & 2u)) << 62);
        u64 m1 = (((u64)(nib & 4u)) << 29) | (((u64)(nib & 8u)) << 60);
        va[2*q]   = pack2(fa.x, fa.y) ^ m0;
        va[2*q+1] = pack2(fa.z, fa.w) ^ m1;
        vb[2*q]   = pack2(fb.x, fb.y) ^ m0;
        vb[2*q+1] = pack2(fb.z, fb.w) ^ m1;
    }

    // ---- WHT#1a over e-bits {0,1,7,8,9} ----
    fwht32(va); fwht32(vb);

    // ---- crossing 1: natural -> QB (regs become e-bits {2..6}); STS.128 words ----
    #pragma unroll
    for (int q = 0; q < 8; q++) {
        float a0, a1, a2, a3, b0, b1, b2, b3;
        unpack2(va[2*q],   a0, a1);
        unpack2(va[2*q+1], a2, a3);
        unpack2(vb[2*q],   b0, b1);
        unpack2(vb[2*q+1], b2, b3);
        sw4[q * 32 + (lane ^ q)] = make_uint4(mkw(a0,b0), mkw(a1,b1), mkw(a2,b2), mkw(a3,b3));
    }
    __syncwarp();
    {
        const unsigned* cbase = sw + qr * 128 + br;
        #pragma unroll
        for (int k = 0; k < 16; k++) {
            unsigned w0 = cbase[((2*k)     ^ qr) << 2];   // conflict-free LDS.32
            unsigned w1 = cbase[((2*k + 1) ^ qr) << 2];
            va[k] = pack2(wlo(w0), wlo(w1));
            vb[k] = pack2(whi(w0), whi(w1));
        }
    }

    // ---- WHT#1b over e-bits {2..6}: HBx complete ----
    fwht32(va); fwht32(vb);
    __syncwarp();   // crossing-1 reads done before scatter overwrites

    // ---- crossing 2 (permutation): scatter packed words to gather slots ----
    const uint4* Qs4 = reinterpret_cast<const uint4*>(g_Qs);
    #pragma unroll
    for (int j = 0; j < 4; j++) {          // mw = 8j .. 8j+7  -> v[4j .. 4j+3]
        uint4 q = Qs4[j * 32 + lane];
        float a0, a1, a2, a3, a4, a5, a6, a7;
        float b0, b1, b2, b3, b4, b5, b6, b7;
        unpack2(va[4*j],   a0, a1);  unpack2(vb[4*j],   b0, b1);
        unpack2(va[4*j+1], a2, a3);  unpack2(vb[4*j+1], b2, b3);
        unpack2(va[4*j+2], a4, a5);  unpack2(vb[4*j+2], b4, b5);
        unpack2(va[4*j+3], a6, a7);  unpack2(vb[4*j+3], b6, b7);
        sw[q.x & 0xffffu] = mkw(a0, b0);  sw[q.x >> 16] = mkw(a1, b1);
        sw[q.y & 0xffffu] = mkw(a2, b2);  sw[q.y >> 16] = mkw(a3, b3);
        sw[q.z & 0xffffu] = mkw(a4, b4);  sw[q.z >> 16] = mkw(a5, b5);
        sw[q.w & 0xffffu] = mkw(a6, b6);  sw[q.w >> 16] = mkw(a7, b7);
    }
    __syncwarp();

    // ---- gather (QB ownership of t, regs = t-bits {2..6}), multiply G ----
    const uint2* Gv2 = reinterpret_cast<const uint2*>(g_Gh);
    #pragma unroll
    for (int j = 0; j < 8; j++) {
        uint4 f = sw4[lane * 8 + ((j ^ lane) & 7)];   // conflict-free LDS.128
        uint2 g = Gv2[j * 32 + lane];                 // coalesced fp16 G
        float2 g01 = __half22float2(u2h(g.x)), g23 = __half22float2(u2h(g.y));
        u64 G01 = pack2(g01.x, g01.y), G23 = pack2(g23.x, g23.y);
        va[2*j]   = mul2(pack2(wlo(f.x), wlo(f.y)), G01);
        va[2*j+1] = mul2(pack2(wlo(f.z), wlo(f.w)), G23);
        vb[2*j]   = mul2(pack2(whi(f.x), whi(f.y)), G01);
        vb[2*j+1] = mul2(pack2(whi(f.z), whi(f.w)), G23);
    }

    // ---- WHT#2a over t-bits {2..6} ----
    fwht32(va); fwht32(vb);
    __syncwarp();   // gather reads done before crossing-3 writes

    // ---- crossing 3: QB -> natural (regs become t-bits {0,1,7,8,9}) ----
    {
        unsigned* cbase = sw + qr * 128 + br;
        #pragma unroll
        for (int k = 0; k < 16; k++) {
            float a0, a1, b0, b1;
            unpack2(va[k], a0, a1);
            unpack2(vb[k], b0, b1);
            cbase[((2*k)     ^ qr) << 2] = mkw(a0, b0);   // conflict-free STS.32
            cbase[((2*k + 1) ^ qr) << 2] = mkw(a1, b1);
        }
    }
    __syncwarp();
    #pragma unroll
    for (int q = 0; q < 8; q++) {
        uint4 f = sw4[q * 32 + (lane ^ q)];   // conflict-free LDS.128
        va[2*q]   = pack2(wlo(f.x), wlo(f.y));
        va[2*q+1] = pack2(wlo(f.z), wlo(f.w));
        vb[2*q]   = pack2(whi(f.x), whi(f.y));
        vb[2*q+1] = pack2(whi(f.z), whi(f.w));
    }

    // ---- WHT#2b over t-bits {0,1,7,8,9}: transform complete ----
    fwht32(va); fwht32(vb);

    // ---- x S/32 (fp16 natural table), coalesced float4 stores for both rows ----
    const uint2* Sv2 = reinterpret_cast<const uint2*>(g_Sh);
    float4* oa = reinterpret_cast<float4*>(out) + (size_t)(pair * 2) * (D / 4) + lane;
    float4* ob = oa + (D / 4);
    #pragma unroll
    for (int q = 0; q < 8; q++) {
        uint2 su = Sv2[q * 32 + lane];
        float2 s01 = __half22float2(u2h(su.x)), s23 = __half22float2(u2h(su.y));
        u64 S01 = pack2(s01.x, s01.y), S23 = pack2(s23.x, s23.y);
        u64 ra0 = mul2(va[2*q], S01), ra1 = mul2(va[2*q+1], S23);
        u64 rb0 = mul2(vb[2*q], S01), rb1 = mul2(vb[2*q+1], S23);
        float p0, p1, p2, p3;
        unpack2(ra0, p0, p1); unpack2(ra1, p2, p3);
        oa[q * 32] = make_float4(p0, p1, p2, p3);
        unpack2(rb0, p0, p1); unpack2(rb1, p2, p3);
        ob[q * 32] = make_float4(p0, p1, p2, p3);
    }
}

extern "C" void kernel_launch(void* const* d_in, const int* in_sizes, int n_in,
                              void* d_out, int out_size) {
    const float* x = (const float*)d_in[0];
    const float* B = (const float*)d_in[1];
    const float* G = (const float*)d_in[2];
    const float* S = (const float*)d_in[3];
    const int*   P = (const int*)d_in[4];
    float* out = (float*)d_out;

    const int nrows = in_sizes[0] / D;

    fastfood_prep<<<(D + 255) / 256, 256>>>(P, B, G, S);

    const int rows_per_block = WARPS * 2;
    const int blocks = (nrows + rows_per_block - 1) / rows_per_block;
    fastfood_kernel<<<blocks, WARPS * 32>>>(x, out, nrows);
}

// round 17
// speedup vs baseline: 1.5165x; 1.5165x over previous
#include <cuda_runtime.h>
#include <cuda_fp16.h>
#include <cstdint>

#define D 1024
#define WARPS 4          // warps per block (128 threads), 2 rows per warp

typedef unsigned long long u64;

// ---------- packed f32x2 helpers (sm_103a) ----------
__device__ __forceinline__ u64 pack2(float a, float b) {
    u64 r; asm("mov.b64 %0, {%1, %2};" : "=l"(r) : "f"(a), "f"(b)); return r;
}
__device__ __forceinline__ void unpack2(u64 v, float& a, float& b) {
    asm("mov.b64 {%0, %1}, %2;" : "=f"(a), "=f"(b) : "l"(v));
}
__device__ __forceinline__ u64 add2(u64 a, u64 b) {
    u64 r; asm("add.rn.f32x2 %0, %1, %2;" : "=l"(r) : "l"(a), "l"(b)); return r;
}
__device__ __forceinline__ u64 mul2(u64 a, u64 b) {
    u64 r; asm("mul.rn.f32x2 %0, %1, %2;" : "=l"(r) : "l"(a), "l"(b)); return r;
}
__device__ __forceinline__ u64 fma2(u64 a, u64 b, u64 c) {
    u64 r; asm("fma.rn.f32x2 %0, %1, %2, %3;" : "=l"(r) : "l"(a), "l"(b), "l"(c)); return r;
}
__device__ __forceinline__ unsigned h2u(__half2 h) { return *reinterpret_cast<unsigned*>(&h); }
__device__ __forceinline__ __half2 u2h(unsigned u) { return *reinterpret_cast<__half2*>(&u); }
// word w = {lo: rowA, hi: rowB}
__device__ __forceinline__ unsigned mkw(float a, float b) { return h2u(__floats2half2_rn(a, b)); }
__device__ __forceinline__ float wlo(unsigned w) { return __low2float(u2h(w)); }
__device__ __forceinline__ float whi(unsigned w) { return __high2float(u2h(w)); }

// FWHT over the 32-value register axis. v[k] packs index i = 2k (lo), 2k+1 (hi).
__device__ __forceinline__ void fwht32(u64 v[16]) {
    const u64 NEG1 = 0xBF800000BF800000ULL;  // (-1.f, -1.f)
    #pragma unroll
    for (int k = 0; k < 16; k++) {
        float a, b; unpack2(v[k], a, b);
        v[k] = pack2(a + b, a - b);
    }
    #pragma unroll
    for (int h = 1; h <= 8; h <<= 1) {
        #pragma unroll
        for (int k = 0; k < 16; k++) {
            if (!(k & h)) {
                u64 A = v[k], B = v[k + h];
                v[k]     = add2(A, B);
                v[k + h] = fma2(B, NEG1, A);
            }
        }
    }
}

// Ownerships: "natural": lane owns z = q*128 + 4*lane + b, regs i = b|(q<<2)
// (= z-bits {0,1,7,8,9}).  "QB": lane = ((z>>7)<<2)|(z&3), regs m = (z>>2)&31.
// All smem in u32 words (one per element, 2 rows packed), word-granularity
// conflict-free layouts.

// Precomputed tables (allocation-free scratch):
__device__ unsigned short g_Qs[D];   // scatter targets (u32-word slot indices)
__device__ __half         g_Gh[D];   // G[t], gather-owner layout (fp16)
__device__ __half         g_Sh[D];   // S[t]/32, natural order (fp16)
__device__ unsigned       g_Bbits[32];  // sign bits of B, natural ownership

__global__ void fastfood_prep(const int* __restrict__ P, const float* __restrict__ B,
                              const float* __restrict__ G, const float* __restrict__ S) {
    int t = blockIdx.x * blockDim.x + threadIdx.x;
    if (t < D) {
        int e  = P[t];
        int w  = ((e >> 7) << 2) | (e & 3);   // writer lane of e (QB)
        int mw = (e >> 2) & 31;               // writer reg of e
        int L  = ((t >> 7) << 2) | (t & 3);   // gather owner lane of t (QB)
        int mm = (t >> 2) & 31;               // gather reg of t
        // gather layout (word units): lane L's 32 words contiguous, uint4-column XOR swizzle
        int slot = L * 32 + ((((mm >> 2) ^ (L & 7)) & 7) << 2) + (mm & 3);
        g_Qs[(mw >> 3) * 256 + w * 8 + (mw & 7)] = (unsigned short)slot;
        g_Gh[((mm >> 2) * 32 + L) * 4 + (mm & 3)] = __float2half(G[t]);
        g_Sh[t] = __float2half(S[t] * 0.03125f);   // 1/sqrt(1024), SCALE=1
    }
    if (t < 32) {
        unsigned bits = 0;
        for (int q = 0; q < 8; q++)
            for (int b = 0; b < 4; b++)
                if (B[q * 128 + 4 * t + b] < 0.0f) bits |= 1u << (4 * q + b);
        g_Bbits[t] = bits;
    }
}

__global__ __launch_bounds__(WARPS * 32, 4)
void fastfood_kernel(const float* __restrict__ x, float* __restrict__ out, int nrows) {
    __shared__ __align__(16) unsigned buf[WARPS][D];   // 4 KB/warp, 16 KB/block
    const int warp = threadIdx.x >> 5;
    const int lane = threadIdx.x & 31;
    const int pair = blockIdx.x * WARPS + warp;
    if (pair * 2 >= nrows) return;

    unsigned* sw  = buf[warp];
    uint4*    sw4 = reinterpret_cast<uint4*>(sw);
    const int qr = lane >> 2, br = lane & 3;

    const unsigned bb = g_Bbits[lane];

    u64 va[16], vb[16];

    // ---- load both rows, apply B as sign-bit XOR (natural ownership of e) ----
    const float4* xa = reinterpret_cast<const float4*>(x) + (size_t)(pair * 2) * (D / 4) + lane;
    const float4* xb = xa + (D / 4);
    #pragma unroll
    for (int q = 0; q < 8; q++) {
        float4 fa = xa[q * 32];
        float4 fb = xb[q * 32];
        unsigned nib = bb >> (4 * q);
        u64 m0 = (((u64)(nib & 1u)) << 31) | (((u64)(nib & 2u)) << 62);
        u64 m1 = (((u64)(nib & 4u)) << 29) | (((u64)(nib & 8u)) << 60);
        va[2*q]   = pack2(fa.x, fa.y) ^ m0;
        va[2*q+1] = pack2(fa.z, fa.w) ^ m1;
        vb[2*q]   = pack2(fb.x, fb.y) ^ m0;
        vb[2*q+1] = pack2(fb.z, fb.w) ^ m1;
    }

    // ---- WHT#1a over e-bits {0,1,7,8,9} ----
    fwht32(va); fwht32(vb);

    // ---- crossing 1: natural -> QB (regs become e-bits {2..6}); STS.128 words ----
    #pragma unroll
    for (int q = 0; q < 8; q++) {
        float a0, a1, a2, a3, b0, b1, b2, b3;
        unpack2(va[2*q],   a0, a1);
        unpack2(va[2*q+1], a2, a3);
        unpack2(vb[2*q],   b0, b1);
        unpack2(vb[2*q+1], b2, b3);
        sw4[q * 32 + (lane ^ q)] = make_uint4(mkw(a0,b0), mkw(a1,b1), mkw(a2,b2), mkw(a3,b3));
    }
    __syncwarp();
    {
        const unsigned* cbase = sw + qr * 128 + br;
        #pragma unroll
        for (int k = 0; k < 16; k++) {
            unsigned w0 = cbase[((2*k)     ^ qr) << 2];   // conflict-free LDS.32
            unsigned w1 = cbase[((2*k + 1) ^ qr) << 2];
            va[k] = pack2(wlo(w0), wlo(w1));
            vb[k] = pack2(whi(w0), whi(w1));
        }
    }

    // ---- WHT#1b over e-bits {2..6}: HBx complete ----
    fwht32(va); fwht32(vb);
    __syncwarp();   // crossing-1 reads done before scatter overwrites

    // ---- crossing 2 (permutation): scatter packed words to gather slots ----
    const uint4* Qs4 = reinterpret_cast<const uint4*>(g_Qs);
    #pragma unroll
    for (int j = 0; j < 4; j++) {          // mw = 8j .. 8j+7  -> v[4j .. 4j+3]
        uint4 q = Qs4[j * 32 + lane];
        float a0, a1, a2, a3, a4, a5, a6, a7;
        float b0, b1, b2, b3, b4, b5, b6, b7;
        unpack2(va[4*j],   a0, a1);  unpack2(vb[4*j],   b0, b1);
        unpack2(va[4*j+1], a2, a3);  unpack2(vb[4*j+1], b2, b3);
        unpack2(va[4*j+2], a4, a5);  unpack2(vb[4*j+2], b4, b5);
        unpack2(va[4*j+3], a6, a7);  unpack2(vb[4*j+3], b6, b7);
        sw[q.x & 0xffffu] = mkw(a0, b0);  sw[q.x >> 16] = mkw(a1, b1);
        sw[q.y & 0xffffu] = mkw(a2, b2);  sw[q.y >> 16] = mkw(a3, b3);
        sw[q.z & 0xffffu] = mkw(a4, b4);  sw[q.z >> 16] = mkw(a5, b5);
        sw[q.w & 0xffffu] = mkw(a6, b6);  sw[q.w >> 16] = mkw(a7, b7);
    }
    __syncwarp();

    // ---- gather (QB ownership of t, regs = t-bits {2..6}), multiply G ----
    const uint2* Gv2 = reinterpret_cast<const uint2*>(g_Gh);
    #pragma unroll
    for (int j = 0; j < 8; j++) {
        uint4 f = sw4[lane * 8 + ((j ^ lane) & 7)];   // conflict-free LDS.128
        uint2 g = Gv2[j * 32 + lane];                 // coalesced fp16 G
        float2 g01 = __half22float2(u2h(g.x)), g23 = __half22float2(u2h(g.y));
        u64 G01 = pack2(g01.x, g01.y), G23 = pack2(g23.x, g23.y);
        va[2*j]   = mul2(pack2(wlo(f.x), wlo(f.y)), G01);
        va[2*j+1] = mul2(pack2(wlo(f.z), wlo(f.w)), G23);
        vb[2*j]   = mul2(pack2(whi(f.x), whi(f.y)), G01);
        vb[2*j+1] = mul2(pack2(whi(f.z), whi(f.w)), G23);
    }

    // ---- WHT#2a over t-bits {2..6} ----
    fwht32(va); fwht32(vb);
    __syncwarp();   // gather reads done before crossing-3 writes

    // ---- crossing 3: QB -> natural (regs become t-bits {0,1,7,8,9}) ----
    {
        unsigned* cbase = sw + qr * 128 + br;
        #pragma unroll
        for (int k = 0; k < 16; k++) {
            float a0, a1, b0, b1;
            unpack2(va[k], a0, a1);
            unpack2(vb[k], b0, b1);
            cbase[((2*k)     ^ qr) << 2] = mkw(a0, b0);   // conflict-free STS.32
            cbase[((2*k + 1) ^ qr) << 2] = mkw(a1, b1);
        }
    }
    __syncwarp();
    #pragma unroll
    for (int q = 0; q < 8; q++) {
        uint4 f = sw4[q * 32 + (lane ^ q)];   // conflict-free LDS.128
        va[2*q]   = pack2(wlo(f.x), wlo(f.y));
        va[2*q+1] = pack2(wlo(f.z), wlo(f.w));
        vb[2*q]   = pack2(whi(f.x), whi(f.y));
        vb[2*q+1] = pack2(whi(f.z), whi(f.w));
    }

    // ---- WHT#2b over t-bits {0,1,7,8,9}: transform complete ----
    fwht32(va); fwht32(vb);

    // ---- x S/32 (fp16 natural table), coalesced float4 stores for both rows ----
    const uint2* Sv2 = reinterpret_cast<const uint2*>(g_Sh);
    float4* oa = reinterpret_cast<float4*>(out) + (size_t)(pair * 2) * (D / 4) + lane;
    float4* ob = oa + (D / 4);
    #pragma unroll
    for (int q = 0; q < 8; q++) {
        uint2 su = Sv2[q * 32 + lane];
        float2 s01 = __half22float2(u2h(su.x)), s23 = __half22float2(u2h(su.y));
        u64 S01 = pack2(s01.x, s01.y), S23 = pack2(s23.x, s23.y);
        u64 ra0 = mul2(va[2*q], S01), ra1 = mul2(va[2*q+1], S23);
        u64 rb0 = mul2(vb[2*q], S01), rb1 = mul2(vb[2*q+1], S23);
        float p0, p1, p2, p3;
        unpack2(ra0, p0, p1); unpack2(ra1, p2, p3);
        oa[q * 32] = make_float4(p0, p1, p2, p3);
        unpack2(rb0, p0, p1); unpack2(rb1, p2, p3);
        ob[q * 32] = make_float4(p0, p1, p2, p3);
    }
}

extern "C" void kernel_launch(void* const* d_in, const int* in_sizes, int n_in,
                              void* d_out, int out_size) {
    const float* x = (const float*)d_in[0];
    const float* B = (const float*)d_in[1];
    const float* G = (const float*)d_in[2];
    const float* S = (const float*)d_in[3];
    const int*   P = (const int*)d_in[4];
    float* out = (float*)d_out;

    const int nrows = in_sizes[0] / D;

    fastfood_prep<<<(D + 255) / 256, 256>>>(P, B, G, S);

    const int rows_per_block = WARPS * 2;
    const int blocks = (nrows + rows_per_block - 1) / rows_per_block;
    fastfood_kernel<<<blocks, WARPS * 32>>>(x, out, nrows);
}